// round 1
// baseline (speedup 1.0000x reference)
#include <cuda_runtime.h>
#include <math.h>

#define DD 256
#define SS 16
#define HDIM 64
#define MLPH 1024
#define PSTR 272   // padded stride for k/v smem tiles (16B aligned, reduces bank conflicts)

__device__ __forceinline__ float gelu_tanh(float v) {
    float c = 0.7978845608028654f * (v + 0.044715f * v * v * v);
    return 0.5f * v * (1.0f + tanhf(c));
}

__global__ __launch_bounds__(256) void dtb_kernel(
    const float* __restrict__ hs_g, const float* __restrict__ emb_g,
    const float* __restrict__ W_off, const float* __restrict__ b_off,
    const float* __restrict__ W_kvp, const float* __restrict__ b_kvp,
    const float* __restrict__ Wq, const float* __restrict__ bq,
    const float* __restrict__ Wk, const float* __restrict__ bk,
    const float* __restrict__ Wv, const float* __restrict__ bv,
    const float* __restrict__ Wo, const float* __restrict__ bo,
    const float* __restrict__ ln1s, const float* __restrict__ ln1b,
    const float* __restrict__ ln2s, const float* __restrict__ ln2b,
    const float* __restrict__ W1, const float* __restrict__ b1,
    const float* __restrict__ W2, const float* __restrict__ b2,
    float* __restrict__ out)
{
    __shared__ __align__(16) float hs_sm[DD];
    __shared__ __align__(16) float q_sm[DD];
    __shared__ __align__(16) float attn_sm[DD];
    __shared__ __align__(16) float x_sm[DD];
    __shared__ __align__(16) float off_sm[32];
    __shared__ __align__(16) float p_sm[64];
    __shared__ __align__(16) float red_sm[16];
    __shared__ __align__(16) float kv_sm[SS * DD];      // 16KB: kv tile, later MLP hidden (1024)
    __shared__ __align__(16) float proj_sm[SS * PSTR];  // 17KB: k tile, then v tile, then W2 partials

    const int t  = threadIdx.x;
    const int p  = blockIdx.x;
    const int n  = p >> 12;
    const int hh = (p >> 6) & 63;
    const int ww = p & 63;

    hs_sm[t] = hs_g[(size_t)p * DD + t];
    __syncthreads();

    // ---- 1) offsets: off[s,k] = hs . W_off[:,s,k] + b_off, then 60*sigmoid-30 ----
    {
        int o = t & 31, c = t >> 5;
        float acc = 0.f;
        const float* wp = W_off + o;
        #pragma unroll 8
        for (int d = c * 32; d < c * 32 + 32; ++d)
            acc += hs_sm[d] * wp[d * 32];
        kv_sm[o * 8 + c] = acc;  // scratch
    }
    __syncthreads();
    if (t < 32) {
        float z = b_off[t];
        #pragma unroll
        for (int c = 0; c < 8; ++c) z += kv_sm[t * 8 + c];
        off_sm[t] = 60.0f / (1.0f + expf(-z)) - 30.0f;
    }
    __syncthreads();

    // ---- 2+3) bilinear gather of embedded features + offset embedding -> kv_sm[s][d] ----
    {
        const float wk0 = W_kvp[t], wk1 = W_kvp[DD + t], bkv = b_kvp[t];
        const float* base = emb_g + (size_t)n * 64 * 64 * DD;
        #pragma unroll 4
        for (int s = 0; s < SS; ++s) {
            float oy = off_sm[2 * s], ox = off_sm[2 * s + 1];
            float y = fminf(fmaxf((float)hh + oy, 0.f), 63.f);
            float x = fminf(fmaxf((float)ww + ox, 0.f), 63.f);
            float y0f = floorf(y), x0f = floorf(x);
            float wy = y - y0f, wx = x - x0f;
            int y0 = (int)y0f, x0 = (int)x0f;
            int y1 = min(y0 + 1, 63), x1 = min(x0 + 1, 63);
            float v00 = base[(y0 * 64 + x0) * DD + t];
            float v01 = base[(y0 * 64 + x1) * DD + t];
            float v10 = base[(y1 * 64 + x0) * DD + t];
            float v11 = base[(y1 * 64 + x1) * DD + t];
            float val = (1.f - wy) * ((1.f - wx) * v00 + wx * v01)
                      +        wy  * ((1.f - wx) * v10 + wx * v11);
            kv_sm[s * DD + t] = val + oy * wk0 + ox * wk1 + bkv;
        }
    }

    // ---- 4a) q projection (needs only hs_sm) ----
    {
        float accq = bq[t];
        const float* wp = Wq + t;
        #pragma unroll 4
        for (int d = 0; d < DD; d += 4) {
            float4 hv = *(const float4*)&hs_sm[d];
            accq += hv.x * wp[(d + 0) * DD];
            accq += hv.y * wp[(d + 1) * DD];
            accq += hv.z * wp[(d + 2) * DD];
            accq += hv.w * wp[(d + 3) * DD];
        }
        q_sm[t] = accq;
    }
    __syncthreads();  // kv_sm and q_sm ready

    // ---- 4b) k projection: k[s][t] = kv[s,:] . Wk[:,t] + bk[t] ----
    {
        float acc[SS];
        float bkt = bk[t];
        #pragma unroll
        for (int s = 0; s < SS; ++s) acc[s] = bkt;
        const float* wp = Wk + t;
        for (int d = 0; d < DD; d += 4) {
            float w0 = wp[(d + 0) * DD], w1 = wp[(d + 1) * DD];
            float w2 = wp[(d + 2) * DD], w3 = wp[(d + 3) * DD];
            #pragma unroll
            for (int s = 0; s < SS; ++s) {
                float4 kvv = *(const float4*)&kv_sm[s * DD + d];
                acc[s] += kvv.x * w0 + kvv.y * w1 + kvv.z * w2 + kvv.w * w3;
            }
        }
        #pragma unroll
        for (int s = 0; s < SS; ++s) proj_sm[s * PSTR + t] = acc[s];
    }
    __syncthreads();

    // ---- 4c) scores + softmax over S (threads 0..63; warps 0,1 fully active) ----
    if (t < 64) {
        int a = t >> 4, s = t & 15;
        const float* kr = &proj_sm[s * PSTR + a * HDIM];
        const float* qr = &q_sm[a * HDIM];
        float sc = 0.f;
        #pragma unroll 8
        for (int e = 0; e < HDIM; ++e) sc += qr[e] * kr[e];
        sc *= 0.125f;  // 1/sqrt(64)
        float mx = sc;
        #pragma unroll
        for (int m = 8; m >= 1; m >>= 1)
            mx = fmaxf(mx, __shfl_xor_sync(0xffffffffu, mx, m, 16));
        float ex = expf(sc - mx);
        float sum = ex;
        #pragma unroll
        for (int m = 8; m >= 1; m >>= 1)
            sum += __shfl_xor_sync(0xffffffffu, sum, m, 16);
        p_sm[t] = ex / sum;
    }
    __syncthreads();

    // ---- 4d) v projection (overwrites proj_sm; k no longer needed) ----
    {
        float acc[SS];
        float bvt = bv[t];
        #pragma unroll
        for (int s = 0; s < SS; ++s) acc[s] = bvt;
        const float* wp = Wv + t;
        for (int d = 0; d < DD; d += 4) {
            float w0 = wp[(d + 0) * DD], w1 = wp[(d + 1) * DD];
            float w2 = wp[(d + 2) * DD], w3 = wp[(d + 3) * DD];
            #pragma unroll
            for (int s = 0; s < SS; ++s) {
                float4 kvv = *(const float4*)&kv_sm[s * DD + d];
                acc[s] += kvv.x * w0 + kvv.y * w1 + kvv.z * w2 + kvv.w * w3;
            }
        }
        #pragma unroll
        for (int s = 0; s < SS; ++s) proj_sm[s * PSTR + t] = acc[s];
    }
    __syncthreads();

    // ---- 4e) attn[a,e] = sum_s p[a,s] * v[s,a,e] ----
    {
        int a = t >> 6;
        float acc = 0.f;
        #pragma unroll
        for (int s = 0; s < SS; ++s)
            acc += p_sm[a * 16 + s] * proj_sm[s * PSTR + t];
        attn_sm[t] = acc;
    }
    __syncthreads();

    // ---- 4f) output projection + residual ----
    float resid;
    {
        float o = bo[t];
        const float* wp = Wo + t;
        #pragma unroll 4
        for (int j = 0; j < DD; j += 4) {
            float4 av = *(const float4*)&attn_sm[j];
            o += av.x * wp[(j + 0) * DD] + av.y * wp[(j + 1) * DD]
               + av.z * wp[(j + 2) * DD] + av.w * wp[(j + 3) * DD];
        }
        resid = hs_sm[t] + o;
    }

    // ---- 5a) LayerNorm 1 ----
    {
        float s1 = resid, s2 = resid * resid;
        #pragma unroll
        for (int m = 16; m >= 1; m >>= 1) {
            s1 += __shfl_xor_sync(0xffffffffu, s1, m);
            s2 += __shfl_xor_sync(0xffffffffu, s2, m);
        }
        int wid = t >> 5, lid = t & 31;
        if (lid == 0) { red_sm[wid] = s1; red_sm[8 + wid] = s2; }
        __syncthreads();
        float m1 = 0.f, m2 = 0.f;
        #pragma unroll
        for (int w = 0; w < 8; ++w) { m1 += red_sm[w]; m2 += red_sm[8 + w]; }
        m1 *= (1.f / 256.f);
        m2 = m2 * (1.f / 256.f) - m1 * m1;
        x_sm[t] = (resid - m1) * rsqrtf(m2 + 1e-6f) * ln1s[t] + ln1b[t];
    }
    __syncthreads();

    // ---- 5b) MLP layer 1 + gelu: h[f] for f = 4t..4t+3 (kv_sm reused as h) ----
    {
        float4 acc = *(const float4*)&b1[4 * t];
        const float* wp = W1 + 4 * t;
        #pragma unroll 4
        for (int d = 0; d < DD; ++d) {
            float xd = x_sm[d];
            float4 w = *(const float4*)&wp[d * MLPH];
            acc.x += xd * w.x; acc.y += xd * w.y;
            acc.z += xd * w.z; acc.w += xd * w.w;
        }
        kv_sm[4 * t + 0] = gelu_tanh(acc.x);
        kv_sm[4 * t + 1] = gelu_tanh(acc.y);
        kv_sm[4 * t + 2] = gelu_tanh(acc.z);
        kv_sm[4 * t + 3] = gelu_tanh(acc.w);
    }
    __syncthreads();

    // ---- 5c) MLP layer 2: 4 f-chunks x 64 output-groups of 4 (partials in proj_sm) ----
    {
        int og = t & 63, c = t >> 6;
        float4 acc = make_float4(0.f, 0.f, 0.f, 0.f);
        const float* wp = W2 + 4 * og;
        #pragma unroll 4
        for (int f = c * 256; f < c * 256 + 256; ++f) {
            float hv = kv_sm[f];
            float4 w = *(const float4*)&wp[f * DD];
            acc.x += hv * w.x; acc.y += hv * w.y;
            acc.z += hv * w.z; acc.w += hv * w.w;
        }
        *(float4*)&proj_sm[4 * t] = acc;  // partial index (c*64+og)*4+i == c*256 + (og*4+i)
    }
    __syncthreads();

    // ---- 5d) combine partials, residual, LayerNorm 2, store ----
    {
        float y = b2[t];
        #pragma unroll
        for (int c = 0; c < 4; ++c) y += proj_sm[c * 256 + t];
        float r2 = x_sm[t] + y;

        float s1 = r2, s2 = r2 * r2;
        #pragma unroll
        for (int m = 16; m >= 1; m >>= 1) {
            s1 += __shfl_xor_sync(0xffffffffu, s1, m);
            s2 += __shfl_xor_sync(0xffffffffu, s2, m);
        }
        int wid = t >> 5, lid = t & 31;
        __syncthreads();  // protect red_sm reuse
        if (lid == 0) { red_sm[wid] = s1; red_sm[8 + wid] = s2; }
        __syncthreads();
        float m1 = 0.f, m2 = 0.f;
        #pragma unroll
        for (int w = 0; w < 8; ++w) { m1 += red_sm[w]; m2 += red_sm[8 + w]; }
        m1 *= (1.f / 256.f);
        m2 = m2 * (1.f / 256.f) - m1 * m1;
        out[(size_t)p * DD + t] = (r2 - m1) * rsqrtf(m2 + 1e-6f) * ln2s[t] + ln2b[t];
    }
}

extern "C" void kernel_launch(void* const* d_in, const int* in_sizes, int n_in,
                              void* d_out, int out_size)
{
    const float* hs    = (const float*)d_in[0];
    const float* emb   = (const float*)d_in[1];
    const float* W_off = (const float*)d_in[2];
    const float* b_off = (const float*)d_in[3];
    const float* W_kvp = (const float*)d_in[4];
    const float* b_kvp = (const float*)d_in[5];
    const float* Wq = (const float*)d_in[6];  const float* bq = (const float*)d_in[7];
    const float* Wk = (const float*)d_in[8];  const float* bk = (const float*)d_in[9];
    const float* Wv = (const float*)d_in[10]; const float* bv = (const float*)d_in[11];
    const float* Wo = (const float*)d_in[12]; const float* bo = (const float*)d_in[13];
    const float* ln1s = (const float*)d_in[14]; const float* ln1b = (const float*)d_in[15];
    const float *ln2s, *ln2b, *W1, *b1, *W2, *b2;
    if (in_sizes[16] == 256) {
        // setup_inputs dict order: ln2_s, ln2_b, W1, b1, W2, b2
        ln2s = (const float*)d_in[16]; ln2b = (const float*)d_in[17];
        W1   = (const float*)d_in[18]; b1   = (const float*)d_in[19];
        W2   = (const float*)d_in[20]; b2   = (const float*)d_in[21];
    } else {
        // reference signature order: W1, b1, W2, b2, ln2_s, ln2_b
        W1   = (const float*)d_in[16]; b1   = (const float*)d_in[17];
        W2   = (const float*)d_in[18]; b2   = (const float*)d_in[19];
        ln2s = (const float*)d_in[20]; ln2b = (const float*)d_in[21];
    }
    dtb_kernel<<<8192, 256>>>(hs, emb, W_off, b_off, W_kvp, b_kvp,
                              Wq, bq, Wk, bk, Wv, bv, Wo, bo,
                              ln1s, ln1b, ln2s, ln2b, W1, b1, W2, b2,
                              (float*)d_out);
}

// round 2
// speedup vs baseline: 1.3736x; 1.3736x over previous
#include <cuda_runtime.h>
#include <math.h>

#define DD 256
#define SS 16
#define MLPH 1024
#define PIX 4
#define NT 512

// dynamic smem layout (float offsets)
#define KV_OFF   0            // [4][16][256] = 16384   (later: MLP hidden [4][1024])
#define K_OFF    16384        // [4][16][257] = 16448   (later: MLP2 partials [2][1024])
#define CTX_OFF  32832        // [4][4][256]  = 4096
#define HS_OFF   36928        // [4][256]
#define Q_OFF    37952        // [4][256]
#define X_OFF    38976        // [4][256]
#define ATTN_OFF 40000        // [4][256]
#define OFFS_OFF 41024        // [4][32]
#define P_OFF    41152        // [4][64]
#define RED_OFF  41408        // [16][4]
#define SM_FLOATS 41472
#define SM_BYTES  (SM_FLOATS * 4)

__device__ __forceinline__ float gelu_tanh(float v) {
    float c = 0.7978845608028654f * (v + 0.044715f * v * v * v);
    return 0.5f * v * (1.0f + tanhf(c));
}

__global__ __launch_bounds__(NT, 1) void dtb_kernel(
    const float* __restrict__ hs_g, const float* __restrict__ emb_g,
    const float* __restrict__ W_off, const float* __restrict__ b_off,
    const float* __restrict__ W_kvp, const float* __restrict__ b_kvp,
    const float* __restrict__ Wq, const float* __restrict__ bq,
    const float* __restrict__ Wk, const float* __restrict__ bk,
    const float* __restrict__ Wv, const float* __restrict__ bv,
    const float* __restrict__ Wo, const float* __restrict__ bo,
    const float* __restrict__ ln1s, const float* __restrict__ ln1b,
    const float* __restrict__ ln2s, const float* __restrict__ ln2b,
    const float* __restrict__ W1, const float* __restrict__ b1,
    const float* __restrict__ W2, const float* __restrict__ b2,
    float* __restrict__ out)
{
    extern __shared__ float sm[];
    const int t = threadIdx.x;
    const int pbase = blockIdx.x * PIX;
    const int n  = pbase >> 12;
    const int hh = (pbase >> 6) & 63;
    const int wwb = pbase & 63;

    // ---- A) load hidden state for 4 pixels ----
    {
        float2 v = *(const float2*)&hs_g[(size_t)pbase * DD + 2 * t];
        sm[HS_OFF + 2 * t] = v.x;
        sm[HS_OFF + 2 * t + 1] = v.y;
    }
    __syncthreads();

    // ---- B) offsets: 4 pix x 32 outputs, 4-way split reduction ----
    {
        int pix = t >> 7, o = (t >> 2) & 31, c = t & 3;
        const float* hp = sm + HS_OFF + pix * DD + c * 64;
        const float* wp = W_off + (size_t)(c * 64) * 32 + o;
        float acc = 0.f;
        #pragma unroll 16
        for (int d = 0; d < 64; ++d) acc += hp[d] * wp[d * 32];
        acc += __shfl_xor_sync(0xffffffffu, acc, 1);
        acc += __shfl_xor_sync(0xffffffffu, acc, 2);
        if (c == 0) {
            float z = acc + b_off[o];
            sm[OFFS_OFF + pix * 32 + o] = 60.0f / (1.0f + expf(-z)) - 30.0f;
        }
    }
    __syncthreads();

    // ---- C) bilinear gather + offset embedding -> kv ----
    {
        int pp = t >> 8, d = t & 255;
        float wk0 = W_kvp[d], wk1 = W_kvp[DD + d], bkv = b_kvp[d];
        const float* base = emb_g + (size_t)n * 64 * 64 * DD + d;
        float fh = (float)hh;
        #pragma unroll
        for (int q2 = 0; q2 < 2; ++q2) {
            int pix = pp + 2 * q2;
            float fw = (float)(wwb + pix);
            #pragma unroll 4
            for (int s = 0; s < SS; ++s) {
                float oy = sm[OFFS_OFF + pix * 32 + 2 * s];
                float ox = sm[OFFS_OFF + pix * 32 + 2 * s + 1];
                float y = fminf(fmaxf(fh + oy, 0.f), 63.f);
                float x = fminf(fmaxf(fw + ox, 0.f), 63.f);
                float y0f = floorf(y), x0f = floorf(x);
                float wy = y - y0f, wx = x - x0f;
                int y0 = (int)y0f, x0 = (int)x0f;
                int y1 = min(y0 + 1, 63), x1 = min(x0 + 1, 63);
                float v00 = base[(y0 * 64 + x0) * DD];
                float v01 = base[(y0 * 64 + x1) * DD];
                float v10 = base[(y1 * 64 + x0) * DD];
                float v11 = base[(y1 * 64 + x1) * DD];
                float val = (1.f - wy) * ((1.f - wx) * v00 + wx * v01)
                          +        wy  * ((1.f - wx) * v10 + wx * v11);
                sm[KV_OFF + pix * 4096 + s * DD + d] = val + oy * wk0 + ox * wk1 + bkv;
            }
        }
    }

    // ---- D) Q projection (reads only hs, overlap before sync) ----
    {
        int pp = t >> 8, col = t & 255;
        float a0 = bq[col], a1 = a0;
        const float* wp = Wq + col;
        const float* h0 = sm + HS_OFF + pp * DD;
        const float* h1 = h0 + 2 * DD;
        #pragma unroll 4
        for (int d = 0; d < DD; d += 4) {
            float w0 = wp[d * DD], w1 = wp[(d + 1) * DD];
            float w2 = wp[(d + 2) * DD], w3 = wp[(d + 3) * DD];
            float4 v0 = *(const float4*)&h0[d];
            float4 v1 = *(const float4*)&h1[d];
            a0 += v0.x * w0 + v0.y * w1 + v0.z * w2 + v0.w * w3;
            a1 += v1.x * w0 + v1.y * w1 + v1.z * w2 + v1.w * w3;
        }
        sm[Q_OFF + pp * DD + col] = a0;
        sm[Q_OFF + (pp + 2) * DD + col] = a1;
    }
    __syncthreads();

    // ---- E) K projection: thread owns 2 cols x 16 s rows of its pixel ----
    {
        int pix = t >> 7, c0 = (t & 127) * 2;
        float accA[SS], accB[SS];
        float bk0 = bk[c0], bk1 = bk[c0 + 1];
        #pragma unroll
        for (int s = 0; s < SS; ++s) { accA[s] = bk0; accB[s] = bk1; }
        const float* wp = Wk + c0;
        const float* kvp = sm + KV_OFF + pix * 4096;
        for (int d = 0; d < DD; d += 4) {
            float2 w0 = *(const float2*)&wp[d * DD];
            float2 w1 = *(const float2*)&wp[(d + 1) * DD];
            float2 w2 = *(const float2*)&wp[(d + 2) * DD];
            float2 w3 = *(const float2*)&wp[(d + 3) * DD];
            #pragma unroll
            for (int s = 0; s < SS; ++s) {
                float4 kvv = *(const float4*)&kvp[s * DD + d];
                accA[s] += kvv.x * w0.x + kvv.y * w1.x + kvv.z * w2.x + kvv.w * w3.x;
                accB[s] += kvv.x * w0.y + kvv.y * w1.y + kvv.z * w2.y + kvv.w * w3.y;
            }
        }
        float* kp = sm + K_OFF + pix * SS * 257;
        #pragma unroll
        for (int s = 0; s < SS; ++s) {
            kp[s * 257 + c0] = accA[s];
            kp[s * 257 + c0 + 1] = accB[s];
        }
    }
    __syncthreads();

    // ---- F) scores + softmax (256 threads: 4 pix x 4 heads x 16 s) ----
    if (t < 256) {
        int pix = t >> 6, a = (t >> 4) & 3, s = t & 15;
        const float* kr = sm + K_OFF + (pix * SS + s) * 257 + a * 64;
        const float* qr = sm + Q_OFF + pix * DD + a * 64;
        float sc = 0.f;
        #pragma unroll 16
        for (int e = 0; e < 64; ++e) sc += qr[e] * kr[e];
        sc *= 0.125f;
        float mx = sc;
        #pragma unroll
        for (int m = 8; m >= 1; m >>= 1)
            mx = fmaxf(mx, __shfl_xor_sync(0xffffffffu, mx, m, 16));
        float ex = expf(sc - mx);
        float sum = ex;
        #pragma unroll
        for (int m = 8; m >= 1; m >>= 1)
            sum += __shfl_xor_sync(0xffffffffu, sum, m, 16);
        sm[P_OFF + pix * 64 + a * 16 + s] = ex / sum;
    }
    __syncthreads();

    // ---- G) per-head weighted context ctx[pix][a][d] = sum_s p*kv ----
    {
        int pp = t >> 8, d = t & 255;
        #pragma unroll
        for (int q2 = 0; q2 < 2; ++q2) {
            int pix = pp + 2 * q2;
            const float* kvp = sm + KV_OFF + pix * 4096 + d;
            const float* pr = sm + P_OFF + pix * 64;
            float c0 = 0.f, c1 = 0.f, c2 = 0.f, c3 = 0.f;
            #pragma unroll
            for (int s = 0; s < SS; ++s) {
                float kvv = kvp[s * DD];
                c0 += pr[s] * kvv;
                c1 += pr[16 + s] * kvv;
                c2 += pr[32 + s] * kvv;
                c3 += pr[48 + s] * kvv;
            }
            float* cx = sm + CTX_OFF + pix * 1024 + d;
            cx[0] = c0; cx[256] = c1; cx[512] = c2; cx[768] = c3;
        }
    }
    __syncthreads();

    // ---- H1) attn = ctx @ Wv + bv  (softmax weights sum to 1 => bias passes) ----
    {
        int pp = t >> 8, col = t & 255;
        int a = col >> 6;
        float a0 = bv[col], a1 = a0;
        const float* wp = Wv + col;
        const float* c0p = sm + CTX_OFF + pp * 1024 + a * DD;
        const float* c1p = c0p + 2048;
        #pragma unroll 4
        for (int d = 0; d < DD; d += 4) {
            float w0 = wp[d * DD], w1 = wp[(d + 1) * DD];
            float w2 = wp[(d + 2) * DD], w3 = wp[(d + 3) * DD];
            float4 v0 = *(const float4*)&c0p[d];
            float4 v1 = *(const float4*)&c1p[d];
            a0 += v0.x * w0 + v0.y * w1 + v0.z * w2 + v0.w * w3;
            a1 += v1.x * w0 + v1.y * w1 + v1.z * w2 + v1.w * w3;
        }
        sm[ATTN_OFF + pp * DD + col] = a0;
        sm[ATTN_OFF + (pp + 2) * DD + col] = a1;
    }
    __syncthreads();

    // ---- H2) output proj + residual + LayerNorm1 ----
    {
        int pp = t >> 8, col = t & 255;
        float a0 = bo[col], a1 = a0;
        const float* wp = Wo + col;
        const float* at0 = sm + ATTN_OFF + pp * DD;
        const float* at1 = at0 + 2 * DD;
        #pragma unroll 4
        for (int j = 0; j < DD; j += 4) {
            float w0 = wp[j * DD], w1 = wp[(j + 1) * DD];
            float w2 = wp[(j + 2) * DD], w3 = wp[(j + 3) * DD];
            float4 v0 = *(const float4*)&at0[j];
            float4 v1 = *(const float4*)&at1[j];
            a0 += v0.x * w0 + v0.y * w1 + v0.z * w2 + v0.w * w3;
            a1 += v1.x * w0 + v1.y * w1 + v1.z * w2 + v1.w * w3;
        }
        float r0 = sm[HS_OFF + pp * DD + col] + a0;
        float r1 = sm[HS_OFF + (pp + 2) * DD + col] + a1;

        float s1a = r0, s2a = r0 * r0, s1b = r1, s2b = r1 * r1;
        #pragma unroll
        for (int m = 16; m >= 1; m >>= 1) {
            s1a += __shfl_xor_sync(0xffffffffu, s1a, m);
            s2a += __shfl_xor_sync(0xffffffffu, s2a, m);
            s1b += __shfl_xor_sync(0xffffffffu, s1b, m);
            s2b += __shfl_xor_sync(0xffffffffu, s2b, m);
        }
        int wid = t >> 5, lid = t & 31;
        if (lid == 0) {
            float4 rr = make_float4(s1a, s2a, s1b, s2b);
            *(float4*)&sm[RED_OFF + wid * 4] = rr;
        }
        __syncthreads();
        float m1a = 0.f, m2a = 0.f, m1b = 0.f, m2b = 0.f;
        #pragma unroll
        for (int w = 0; w < 8; ++w) {
            float4 rr = *(const float4*)&sm[RED_OFF + (pp * 8 + w) * 4];
            m1a += rr.x; m2a += rr.y; m1b += rr.z; m2b += rr.w;
        }
        m1a *= (1.f / 256.f); m2a = m2a * (1.f / 256.f) - m1a * m1a;
        m1b *= (1.f / 256.f); m2b = m2b * (1.f / 256.f) - m1b * m1b;
        float g = ln1s[col], be = ln1b[col];
        sm[X_OFF + pp * DD + col] = (r0 - m1a) * rsqrtf(m2a + 1e-6f) * g + be;
        sm[X_OFF + (pp + 2) * DD + col] = (r1 - m1b) * rsqrtf(m2b + 1e-6f) * g + be;
    }
    __syncthreads();

    // ---- I) MLP layer 1 + gelu: thread owns 2 hidden cols x 4 pixels ----
    {
        int hc = 2 * t;
        float acc[PIX][2];
        float bb0 = b1[hc], bb1 = b1[hc + 1];
        #pragma unroll
        for (int pix = 0; pix < PIX; ++pix) { acc[pix][0] = bb0; acc[pix][1] = bb1; }
        const float* wp = W1 + hc;
        for (int d = 0; d < DD; d += 4) {
            float2 w0 = *(const float2*)&wp[d * MLPH];
            float2 w1 = *(const float2*)&wp[(d + 1) * MLPH];
            float2 w2 = *(const float2*)&wp[(d + 2) * MLPH];
            float2 w3 = *(const float2*)&wp[(d + 3) * MLPH];
            #pragma unroll
            for (int pix = 0; pix < PIX; ++pix) {
                float4 xv = *(const float4*)&sm[X_OFF + pix * DD + d];
                acc[pix][0] += xv.x * w0.x + xv.y * w1.x + xv.z * w2.x + xv.w * w3.x;
                acc[pix][1] += xv.x * w0.y + xv.y * w1.y + xv.z * w2.y + xv.w * w3.y;
            }
        }
        #pragma unroll
        for (int pix = 0; pix < PIX; ++pix) {
            sm[KV_OFF + pix * MLPH + hc]     = gelu_tanh(acc[pix][0]);
            sm[KV_OFF + pix * MLPH + hc + 1] = gelu_tanh(acc[pix][1]);
        }
    }
    __syncthreads();

    // ---- J) MLP layer 2: split reduction in 2 halves over f ----
    {
        int col = t & 255, hf = t >> 8;
        float acc[PIX] = {0.f, 0.f, 0.f, 0.f};
        const float* wp = W2 + col;
        int f0 = hf * 512;
        for (int f = f0; f < f0 + 512; f += 4) {
            float w0 = wp[f * DD], w1 = wp[(f + 1) * DD];
            float w2 = wp[(f + 2) * DD], w3 = wp[(f + 3) * DD];
            #pragma unroll
            for (int pix = 0; pix < PIX; ++pix) {
                float4 hv = *(const float4*)&sm[KV_OFF + pix * MLPH + f];
                acc[pix] += hv.x * w0 + hv.y * w1 + hv.z * w2 + hv.w * w3;
            }
        }
        #pragma unroll
        for (int pix = 0; pix < PIX; ++pix)
            sm[K_OFF + hf * 1024 + pix * DD + col] = acc[pix];
    }
    __syncthreads();

    // ---- K) combine, residual, LayerNorm2, store ----
    {
        int pp = t >> 8, col = t & 255;
        float bb = b2[col];
        float y0 = bb + sm[K_OFF + pp * DD + col] + sm[K_OFF + 1024 + pp * DD + col];
        float y1 = bb + sm[K_OFF + (pp + 2) * DD + col] + sm[K_OFF + 1024 + (pp + 2) * DD + col];
        float r0 = sm[X_OFF + pp * DD + col] + y0;
        float r1 = sm[X_OFF + (pp + 2) * DD + col] + y1;

        float s1a = r0, s2a = r0 * r0, s1b = r1, s2b = r1 * r1;
        #pragma unroll
        for (int m = 16; m >= 1; m >>= 1) {
            s1a += __shfl_xor_sync(0xffffffffu, s1a, m);
            s2a += __shfl_xor_sync(0xffffffffu, s2a, m);
            s1b += __shfl_xor_sync(0xffffffffu, s1b, m);
            s2b += __shfl_xor_sync(0xffffffffu, s2b, m);
        }
        int wid = t >> 5, lid = t & 31;
        if (lid == 0) {
            float4 rr = make_float4(s1a, s2a, s1b, s2b);
            *(float4*)&sm[RED_OFF + wid * 4] = rr;
        }
        __syncthreads();
        float m1a = 0.f, m2a = 0.f, m1b = 0.f, m2b = 0.f;
        #pragma unroll
        for (int w = 0; w < 8; ++w) {
            float4 rr = *(const float4*)&sm[RED_OFF + (pp * 8 + w) * 4];
            m1a += rr.x; m2a += rr.y; m1b += rr.z; m2b += rr.w;
        }
        m1a *= (1.f / 256.f); m2a = m2a * (1.f / 256.f) - m1a * m1a;
        m1b *= (1.f / 256.f); m2b = m2b * (1.f / 256.f) - m1b * m1b;
        float g = ln2s[col], be = ln2b[col];
        out[((size_t)pbase + pp) * DD + col] =
            (r0 - m1a) * rsqrtf(m2a + 1e-6f) * g + be;
        out[((size_t)pbase + pp + 2) * DD + col] =
            (r1 - m1b) * rsqrtf(m2b + 1e-6f) * g + be;
    }
}

extern "C" void kernel_launch(void* const* d_in, const int* in_sizes, int n_in,
                              void* d_out, int out_size)
{
    const float* hs    = (const float*)d_in[0];
    const float* emb   = (const float*)d_in[1];
    const float* W_off = (const float*)d_in[2];
    const float* b_off = (const float*)d_in[3];
    const float* W_kvp = (const float*)d_in[4];
    const float* b_kvp = (const float*)d_in[5];
    const float* Wq = (const float*)d_in[6];  const float* bq = (const float*)d_in[7];
    const float* Wk = (const float*)d_in[8];  const float* bk = (const float*)d_in[9];
    const float* Wv = (const float*)d_in[10]; const float* bv = (const float*)d_in[11];
    const float* Wo = (const float*)d_in[12]; const float* bo = (const float*)d_in[13];
    const float* ln1s = (const float*)d_in[14]; const float* ln1b = (const float*)d_in[15];
    const float *ln2s, *ln2b, *W1, *b1, *W2, *b2;
    if (in_sizes[16] == 256) {
        ln2s = (const float*)d_in[16]; ln2b = (const float*)d_in[17];
        W1   = (const float*)d_in[18]; b1   = (const float*)d_in[19];
        W2   = (const float*)d_in[20]; b2   = (const float*)d_in[21];
    } else {
        W1   = (const float*)d_in[16]; b1   = (const float*)d_in[17];
        W2   = (const float*)d_in[18]; b2   = (const float*)d_in[19];
        ln2s = (const float*)d_in[20]; ln2b = (const float*)d_in[21];
    }
    cudaFuncSetAttribute(dtb_kernel, cudaFuncAttributeMaxDynamicSharedMemorySize, SM_BYTES);
    dtb_kernel<<<8192 / PIX, NT, SM_BYTES>>>(hs, emb, W_off, b_off, W_kvp, b_kvp,
                                             Wq, bq, Wk, bk, Wv, bv, Wo, bo,
                                             ln1s, ln1b, ln2s, ln2b, W1, b1, W2, b2,
                                             (float*)d_out);
}

// round 3
// speedup vs baseline: 2.3227x; 1.6910x over previous
#include <cuda_runtime.h>
#include <math.h>

#define DD 256
#define SS 16
#define MLPH 1024
#define PIX 8
#define NT 1024
#define KVSTR 264              // padded kv row stride (floats), 16B-aligned
#define KVPIX (SS * KVSTR)     // 4224 floats per pixel

// dynamic smem layout (float offsets)
#define KV_OFF   0             // [8][16][264] = 33792 ; later MLP hidden [8][1024]
#define QW_OFF   33792         // [8][4][256]  = 8192  ; qw -> ctx -> MLP2 partials
#define HS_OFF   41984         // [8][256]
#define Q_OFF    44032         // [8][256] ; later attn
#define X_OFF    46080         // [8][256]
#define OFFS_OFF 48128         // [8][32]
#define P_OFF    48384         // [8][64]
#define RED_OFF  48896         // [32][4]
#define SM_FLOATS 49024
#define SM_BYTES  (SM_FLOATS * 4)

__device__ __forceinline__ float gelu_tanh(float v) {
    float c = 0.7978845608028654f * (v + 0.044715f * v * v * v);
    return 0.5f * v * (1.0f + tanhf(c));
}

__global__ __launch_bounds__(NT, 1) void dtb_kernel(
    const float* __restrict__ hs_g, const float* __restrict__ emb_g,
    const float* __restrict__ W_off, const float* __restrict__ b_off,
    const float* __restrict__ W_kvp, const float* __restrict__ b_kvp,
    const float* __restrict__ Wq, const float* __restrict__ bq,
    const float* __restrict__ Wk, const float* __restrict__ bk,
    const float* __restrict__ Wv, const float* __restrict__ bv,
    const float* __restrict__ Wo, const float* __restrict__ bo,
    const float* __restrict__ ln1s, const float* __restrict__ ln1b,
    const float* __restrict__ ln2s, const float* __restrict__ ln2b,
    const float* __restrict__ W1, const float* __restrict__ b1,
    const float* __restrict__ W2, const float* __restrict__ b2,
    float* __restrict__ out)
{
    extern __shared__ float sm[];
    const int t = threadIdx.x;
    const int pbase = blockIdx.x * PIX;
    const int n  = pbase >> 12;
    const int hh = (pbase >> 6) & 63;
    const int wwb = pbase & 63;

    // ---- A) load hidden state for 8 pixels ----
    {
        float2 v = *(const float2*)&hs_g[(size_t)pbase * DD + 2 * t];
        sm[HS_OFF + 2 * t] = v.x;
        sm[HS_OFF + 2 * t + 1] = v.y;
    }
    __syncthreads();

    // ---- B) offsets: 8 pix x 32 outputs, 4-way split over d ----
    {
        int pix = t >> 7, o = (t >> 2) & 31, c = t & 3;
        const float* hp = sm + HS_OFF + pix * DD + c * 64;
        const float* wp = W_off + (c * 64) * 32 + o;
        float acc = 0.f;
        #pragma unroll 16
        for (int d = 0; d < 64; ++d) acc += hp[d] * wp[d * 32];
        acc += __shfl_xor_sync(0xffffffffu, acc, 1);
        acc += __shfl_xor_sync(0xffffffffu, acc, 2);
        if (c == 0) {
            float z = acc + b_off[o];
            sm[OFFS_OFF + pix * 32 + o] = 60.0f / (1.0f + expf(-z)) - 30.0f;
        }
    }
    __syncthreads();

    // ---- C) bilinear gather + offset embedding -> kv ----
    {
        int pp = t >> 8, d = t & 255;
        float wk0 = W_kvp[d], wk1 = W_kvp[DD + d], bkv = b_kvp[d];
        const float* base = emb_g + (size_t)n * 64 * 64 * DD + d;
        float fh = (float)hh;
        #pragma unroll
        for (int q2 = 0; q2 < 2; ++q2) {
            int pix = pp + 4 * q2;
            float fw = (float)(wwb + pix);
            #pragma unroll 4
            for (int s = 0; s < SS; ++s) {
                float oy = sm[OFFS_OFF + pix * 32 + 2 * s];
                float ox = sm[OFFS_OFF + pix * 32 + 2 * s + 1];
                float y = fminf(fmaxf(fh + oy, 0.f), 63.f);
                float x = fminf(fmaxf(fw + ox, 0.f), 63.f);
                float y0f = floorf(y), x0f = floorf(x);
                float wy = y - y0f, wx = x - x0f;
                int y0 = (int)y0f, x0 = (int)x0f;
                int y1 = min(y0 + 1, 63), x1 = min(x0 + 1, 63);
                float v00 = base[(y0 * 64 + x0) * DD];
                float v01 = base[(y0 * 64 + x1) * DD];
                float v10 = base[(y1 * 64 + x0) * DD];
                float v11 = base[(y1 * 64 + x1) * DD];
                float val = (1.f - wy) * ((1.f - wx) * v00 + wx * v01)
                          +        wy  * ((1.f - wx) * v10 + wx * v11);
                sm[KV_OFF + pix * KVPIX + s * KVSTR + d] = val + oy * wk0 + ox * wk1 + bkv;
            }
        }
    }

    // ---- D) Q projection (reads only hs; before the kv sync) ----
    {
        int pp = t >> 8, col = t & 255;
        float a0 = bq[col], a1 = a0;
        const float* wp = Wq + col;
        const float* h0 = sm + HS_OFF + pp * DD;
        const float* h1 = sm + HS_OFF + (pp + 4) * DD;
        #pragma unroll 4
        for (int d = 0; d < DD; d += 4) {
            float w0 = wp[d * DD], w1 = wp[(d + 1) * DD];
            float w2 = wp[(d + 2) * DD], w3 = wp[(d + 3) * DD];
            float4 v0 = *(const float4*)&h0[d];
            float4 v1 = *(const float4*)&h1[d];
            a0 += v0.x * w0 + v0.y * w1 + v0.z * w2 + v0.w * w3;
            a1 += v1.x * w0 + v1.y * w1 + v1.z * w2 + v1.w * w3;
        }
        sm[Q_OFF + pp * DD + col] = a0;
        sm[Q_OFF + (pp + 4) * DD + col] = a1;
    }
    __syncthreads();

    // ---- E) qw[pix][a][d] = sum_e q[pix][a*64+e] * Wk[d][a][e]  (bk cancels in softmax) ----
    {
        int a = t >> 8, d = t & 255;
        float acc[PIX];
        #pragma unroll
        for (int pix = 0; pix < PIX; ++pix) acc[pix] = 0.f;
        const float* wp = Wk + d * DD + a * 64;
        const float* qp = sm + Q_OFF + a * 64;
        #pragma unroll 4
        for (int e = 0; e < 64; e += 4) {
            float4 w = *(const float4*)&wp[e];
            #pragma unroll
            for (int pix = 0; pix < PIX; ++pix) {
                float4 qv = *(const float4*)&qp[pix * DD + e];
                acc[pix] += qv.x * w.x + qv.y * w.y + qv.z * w.z + qv.w * w.w;
            }
        }
        #pragma unroll
        for (int pix = 0; pix < PIX; ++pix)
            sm[QW_OFF + pix * 1024 + a * DD + d] = acc[pix];
    }
    __syncthreads();

    // ---- F) scores + softmax: 512 threads = 8 pix x 4 heads x 16 s ----
    if (t < 512) {
        int s = t & 15, a = (t >> 4) & 3, pix = t >> 6;
        const float* kvp = sm + KV_OFF + pix * KVPIX + s * KVSTR;
        const float* qwp = sm + QW_OFF + pix * 1024 + a * DD;
        float sc = 0.f;
        #pragma unroll 8
        for (int d = 0; d < DD; d += 4) {
            float4 kvv = *(const float4*)&kvp[d];
            float4 qw4 = *(const float4*)&qwp[d];
            sc += kvv.x * qw4.x + kvv.y * qw4.y + kvv.z * qw4.z + kvv.w * qw4.w;
        }
        sc *= 0.125f;
        float mx = sc;
        #pragma unroll
        for (int m = 8; m >= 1; m >>= 1)
            mx = fmaxf(mx, __shfl_xor_sync(0xffffffffu, mx, m, 16));
        float ex = expf(sc - mx);
        float sum = ex;
        #pragma unroll
        for (int m = 8; m >= 1; m >>= 1)
            sum += __shfl_xor_sync(0xffffffffu, sum, m, 16);
        sm[P_OFF + pix * 64 + a * 16 + s] = ex / sum;
    }
    __syncthreads();

    // ---- G) ctx[pix][a][d] = sum_s p[a,s] * kv[s,d]  (overwrites qw) ----
    {
        int pp = t >> 8, d = t & 255;
        #pragma unroll
        for (int q2 = 0; q2 < 2; ++q2) {
            int pix = pp + 4 * q2;
            const float* kvp = sm + KV_OFF + pix * KVPIX + d;
            const float* pr = sm + P_OFF + pix * 64;
            float c0 = 0.f, c1 = 0.f, c2 = 0.f, c3 = 0.f;
            #pragma unroll
            for (int s = 0; s < SS; ++s) {
                float kvv = kvp[s * KVSTR];
                c0 += pr[s] * kvv;
                c1 += pr[16 + s] * kvv;
                c2 += pr[32 + s] * kvv;
                c3 += pr[48 + s] * kvv;
            }
            float* cx = sm + QW_OFF + pix * 1024 + d;
            cx[0] = c0; cx[256] = c1; cx[512] = c2; cx[768] = c3;
        }
    }
    __syncthreads();

    // ---- H1) attn = ctx @ Wv + bv (softmax weights sum to 1) -> Q buffer ----
    {
        int pp = t >> 8, col = t & 255;
        int a = col >> 6;
        float a0 = bv[col], a1 = a0;
        const float* wp = Wv + col;
        const float* c0p = sm + QW_OFF + pp * 1024 + a * DD;
        const float* c1p = sm + QW_OFF + (pp + 4) * 1024 + a * DD;
        #pragma unroll 4
        for (int d = 0; d < DD; d += 4) {
            float w0 = wp[d * DD], w1 = wp[(d + 1) * DD];
            float w2 = wp[(d + 2) * DD], w3 = wp[(d + 3) * DD];
            float4 v0 = *(const float4*)&c0p[d];
            float4 v1 = *(const float4*)&c1p[d];
            a0 += v0.x * w0 + v0.y * w1 + v0.z * w2 + v0.w * w3;
            a1 += v1.x * w0 + v1.y * w1 + v1.z * w2 + v1.w * w3;
        }
        sm[Q_OFF + pp * DD + col] = a0;
        sm[Q_OFF + (pp + 4) * DD + col] = a1;
    }
    __syncthreads();

    // ---- H2) output proj + residual + LayerNorm1 -> x ----
    {
        int pp = t >> 8, col = t & 255;
        float a0 = bo[col], a1 = a0;
        const float* wp = Wo + col;
        const float* at0 = sm + Q_OFF + pp * DD;
        const float* at1 = sm + Q_OFF + (pp + 4) * DD;
        #pragma unroll 4
        for (int j = 0; j < DD; j += 4) {
            float w0 = wp[j * DD], w1 = wp[(j + 1) * DD];
            float w2 = wp[(j + 2) * DD], w3 = wp[(j + 3) * DD];
            float4 v0 = *(const float4*)&at0[j];
            float4 v1 = *(const float4*)&at1[j];
            a0 += v0.x * w0 + v0.y * w1 + v0.z * w2 + v0.w * w3;
            a1 += v1.x * w0 + v1.y * w1 + v1.z * w2 + v1.w * w3;
        }
        float r0 = sm[HS_OFF + pp * DD + col] + a0;
        float r1 = sm[HS_OFF + (pp + 4) * DD + col] + a1;

        float s1a = r0, s2a = r0 * r0, s1b = r1, s2b = r1 * r1;
        #pragma unroll
        for (int m = 16; m >= 1; m >>= 1) {
            s1a += __shfl_xor_sync(0xffffffffu, s1a, m);
            s2a += __shfl_xor_sync(0xffffffffu, s2a, m);
            s1b += __shfl_xor_sync(0xffffffffu, s1b, m);
            s2b += __shfl_xor_sync(0xffffffffu, s2b, m);
        }
        int wid = t >> 5, lid = t & 31;
        if (lid == 0)
            *(float4*)&sm[RED_OFF + wid * 4] = make_float4(s1a, s2a, s1b, s2b);
        __syncthreads();
        float m1a = 0.f, m2a = 0.f, m1b = 0.f, m2b = 0.f;
        #pragma unroll
        for (int w = 0; w < 8; ++w) {
            float4 rr = *(const float4*)&sm[RED_OFF + (pp * 8 + w) * 4];
            m1a += rr.x; m2a += rr.y; m1b += rr.z; m2b += rr.w;
        }
        m1a *= (1.f / 256.f); m2a = m2a * (1.f / 256.f) - m1a * m1a;
        m1b *= (1.f / 256.f); m2b = m2b * (1.f / 256.f) - m1b * m1b;
        float g = ln1s[col], be = ln1b[col];
        sm[X_OFF + pp * DD + col] = (r0 - m1a) * rsqrtf(m2a + 1e-6f) * g + be;
        sm[X_OFF + (pp + 4) * DD + col] = (r1 - m1b) * rsqrtf(m2b + 1e-6f) * g + be;
    }
    __syncthreads();

    // ---- I) MLP1 + gelu: thread owns hidden col t for all 8 pixels (kv buffer reused) ----
    {
        float acc[PIX];
        float bb = b1[t];
        #pragma unroll
        for (int pix = 0; pix < PIX; ++pix) acc[pix] = bb;
        const float* wp = W1 + t;
        for (int d = 0; d < DD; d += 4) {
            float w0 = wp[d * MLPH], w1 = wp[(d + 1) * MLPH];
            float w2 = wp[(d + 2) * MLPH], w3 = wp[(d + 3) * MLPH];
            #pragma unroll
            for (int pix = 0; pix < PIX; ++pix) {
                float4 xv = *(const float4*)&sm[X_OFF + pix * DD + d];
                acc[pix] += xv.x * w0 + xv.y * w1 + xv.z * w2 + xv.w * w3;
            }
        }
        #pragma unroll
        for (int pix = 0; pix < PIX; ++pix)
            sm[KV_OFF + pix * MLPH + t] = gelu_tanh(acc[pix]);
    }
    __syncthreads();

    // ---- J) MLP2: 4-way split over f; partials into QW buffer ----
    {
        int col = t & 255, c = t >> 8;
        float acc[PIX];
        #pragma unroll
        for (int pix = 0; pix < PIX; ++pix) acc[pix] = 0.f;
        const float* wp = W2 + col;
        int f0 = c * 256;
        for (int f = f0; f < f0 + 256; f += 4) {
            float w0 = wp[f * DD], w1 = wp[(f + 1) * DD];
            float w2 = wp[(f + 2) * DD], w3 = wp[(f + 3) * DD];
            #pragma unroll
            for (int pix = 0; pix < PIX; ++pix) {
                float4 hv = *(const float4*)&sm[KV_OFF + pix * MLPH + f];
                acc[pix] += hv.x * w0 + hv.y * w1 + hv.z * w2 + hv.w * w3;
            }
        }
        #pragma unroll
        for (int pix = 0; pix < PIX; ++pix)
            sm[QW_OFF + c * 2048 + pix * DD + col] = acc[pix];
    }
    __syncthreads();

    // ---- K) combine partials, residual, LayerNorm2, store ----
    {
        int pp = t >> 8, col = t & 255;
        float bb = b2[col];
        float y0 = bb, y1 = bb;
        #pragma unroll
        for (int c = 0; c < 4; ++c) {
            y0 += sm[QW_OFF + c * 2048 + pp * DD + col];
            y1 += sm[QW_OFF + c * 2048 + (pp + 4) * DD + col];
        }
        float r0 = sm[X_OFF + pp * DD + col] + y0;
        float r1 = sm[X_OFF + (pp + 4) * DD + col] + y1;

        float s1a = r0, s2a = r0 * r0, s1b = r1, s2b = r1 * r1;
        #pragma unroll
        for (int m = 16; m >= 1; m >>= 1) {
            s1a += __shfl_xor_sync(0xffffffffu, s1a, m);
            s2a += __shfl_xor_sync(0xffffffffu, s2a, m);
            s1b += __shfl_xor_sync(0xffffffffu, s1b, m);
            s2b += __shfl_xor_sync(0xffffffffu, s2b, m);
        }
        int wid = t >> 5, lid = t & 31;
        __syncthreads();  // protect RED reuse
        if (lid == 0)
            *(float4*)&sm[RED_OFF + wid * 4] = make_float4(s1a, s2a, s1b, s2b);
        __syncthreads();
        float m1a = 0.f, m2a = 0.f, m1b = 0.f, m2b = 0.f;
        #pragma unroll
        for (int w = 0; w < 8; ++w) {
            float4 rr = *(const float4*)&sm[RED_OFF + (pp * 8 + w) * 4];
            m1a += rr.x; m2a += rr.y; m1b += rr.z; m2b += rr.w;
        }
        m1a *= (1.f / 256.f); m2a = m2a * (1.f / 256.f) - m1a * m1a;
        m1b *= (1.f / 256.f); m2b = m2b * (1.f / 256.f) - m1b * m1b;
        float g = ln2s[col], be = ln2b[col];
        out[((size_t)pbase + pp) * DD + col] =
            (r0 - m1a) * rsqrtf(m2a + 1e-6f) * g + be;
        out[((size_t)pbase + pp + 4) * DD + col] =
            (r1 - m1b) * rsqrtf(m2b + 1e-6f) * g + be;
    }
}

extern "C" void kernel_launch(void* const* d_in, const int* in_sizes, int n_in,
                              void* d_out, int out_size)
{
    const float* hs    = (const float*)d_in[0];
    const float* emb   = (const float*)d_in[1];
    const float* W_off = (const float*)d_in[2];
    const float* b_off = (const float*)d_in[3];
    const float* W_kvp = (const float*)d_in[4];
    const float* b_kvp = (const float*)d_in[5];
    const float* Wq = (const float*)d_in[6];  const float* bq = (const float*)d_in[7];
    const float* Wk = (const float*)d_in[8];  const float* bk = (const float*)d_in[9];
    const float* Wv = (const float*)d_in[10]; const float* bv = (const float*)d_in[11];
    const float* Wo = (const float*)d_in[12]; const float* bo = (const float*)d_in[13];
    const float* ln1s = (const float*)d_in[14]; const float* ln1b = (const float*)d_in[15];
    const float *ln2s, *ln2b, *W1, *b1, *W2, *b2;
    if (in_sizes[16] == 256) {
        ln2s = (const float*)d_in[16]; ln2b = (const float*)d_in[17];
        W1   = (const float*)d_in[18]; b1   = (const float*)d_in[19];
        W2   = (const float*)d_in[20]; b2   = (const float*)d_in[21];
    } else {
        W1   = (const float*)d_in[16]; b1   = (const float*)d_in[17];
        W2   = (const float*)d_in[18]; b2   = (const float*)d_in[19];
        ln2s = (const float*)d_in[20]; ln2b = (const float*)d_in[21];
    }
    (void)bk;
    cudaFuncSetAttribute(dtb_kernel, cudaFuncAttributeMaxDynamicSharedMemorySize, SM_BYTES);
    dtb_kernel<<<8192 / PIX, NT, SM_BYTES>>>(hs, emb, W_off, b_off, W_kvp, b_kvp,
                                             Wq, bq, Wk, bk, Wv, bv, Wo, bo,
                                             ln1s, ln1b, ln2s, ln2b, W1, b1, W2, b2,
                                             (float*)d_out);
}

// round 4
// speedup vs baseline: 2.6221x; 1.1289x over previous
#include <cuda_runtime.h>
#include <math.h>

#define DD 256
#define SS 16
#define MLPH 1024
#define PIX 8
#define NT 1024
#define KVSTR 264              // padded kv row stride (floats)
#define KVPIX (SS * KVSTR)     // 4224 floats per pixel

// dynamic smem layout (float offsets)
#define KV_OFF   0             // [8][16][264]=33792 ; later MLP hidden [8][1024] ; H1/H2 partials [4][8][256]
#define QW_OFF   33792         // 8192: D partials -> qw[8][4][256] -> ctx -> MLP2 partials
#define HS_OFF   41984         // [8][256]
#define Q_OFF    44032         // [8][256] : q -> attn
#define X_OFF    46080         // [8][256]
#define OFFS_OFF 48128         // [8][32]
#define P_OFF    48384         // [8][64]
#define RED_OFF  48896         // [32][4]
#define SM_FLOATS 49024
#define SM_BYTES  (SM_FLOATS * 4)

__device__ float g_WkT[DD * DD];   // WkT[(a*64+e)*256 + d] = 0.125*Wk[d][a][e]

__device__ __forceinline__ float gelu_tanh(float v) {
    float c = 0.7978845608028654f * (v + 0.044715f * v * v * v);
    return 0.5f * v * (1.0f + tanhf(c));
}

__global__ void transpose_wk(const float* __restrict__ Wk) {
    int i = blockIdx.x * 256 + threadIdx.x;   // i = ae*256 + d
    int d = i & 255;
    int ae = i >> 8;
    g_WkT[i] = 0.125f * Wk[d * 256 + ae];
}

__global__ __launch_bounds__(NT, 1) void dtb_kernel(
    const float* __restrict__ hs_g, const float* __restrict__ emb_g,
    const float* __restrict__ W_off, const float* __restrict__ b_off,
    const float* __restrict__ W_kvp, const float* __restrict__ b_kvp,
    const float* __restrict__ Wq, const float* __restrict__ bq,
    const float* __restrict__ Wv, const float* __restrict__ bv,
    const float* __restrict__ Wo, const float* __restrict__ bo,
    const float* __restrict__ ln1s, const float* __restrict__ ln1b,
    const float* __restrict__ ln2s, const float* __restrict__ ln2b,
    const float* __restrict__ W1, const float* __restrict__ b1,
    const float* __restrict__ W2, const float* __restrict__ b2,
    float* __restrict__ out)
{
    extern __shared__ float sm[];
    const int t = threadIdx.x;
    const int pbase = blockIdx.x * PIX;
    const int n  = pbase >> 12;
    const int hh = (pbase >> 6) & 63;
    const int wwb = pbase & 63;

    const int col = t & 255;    // output column for projection stages
    const int dh  = t >> 8;     // 4-way d-split

    // ---- A) load hidden state for 8 pixels ----
    {
        float2 v = *(const float2*)&hs_g[(size_t)pbase * DD + 2 * t];
        sm[HS_OFF + 2 * t] = v.x;
        sm[HS_OFF + 2 * t + 1] = v.y;
    }
    __syncthreads();

    // ---- B) offsets: 8 pix x 32 outputs, 4-way split over d ----
    {
        int pix = t >> 7, o = (t >> 2) & 31, c = t & 3;
        const float* hp = sm + HS_OFF + pix * DD + c * 64;
        const float* wp = W_off + (c * 64) * 32 + o;
        float acc = 0.f;
        #pragma unroll 16
        for (int d = 0; d < 64; ++d) acc += hp[d] * wp[d * 32];
        acc += __shfl_xor_sync(0xffffffffu, acc, 1);
        acc += __shfl_xor_sync(0xffffffffu, acc, 2);
        if (c == 0) {
            float z = acc + b_off[o];
            sm[OFFS_OFF + pix * 32 + o] = 60.0f / (1.0f + expf(-z)) - 30.0f;
        }
    }
    __syncthreads();

    // ---- C) bilinear gather + offset embedding -> kv ----
    {
        int pp = t >> 8, d = t & 255;
        float wk0 = W_kvp[d], wk1 = W_kvp[DD + d], bkv = b_kvp[d];
        const float* base = emb_g + (size_t)n * 64 * 64 * DD + d;
        float fh = (float)hh;
        #pragma unroll
        for (int q2 = 0; q2 < 2; ++q2) {
            int pix = pp + 4 * q2;
            float fw = (float)(wwb + pix);
            #pragma unroll 4
            for (int s = 0; s < SS; ++s) {
                float oy = sm[OFFS_OFF + pix * 32 + 2 * s];
                float ox = sm[OFFS_OFF + pix * 32 + 2 * s + 1];
                float y = fminf(fmaxf(fh + oy, 0.f), 63.f);
                float x = fminf(fmaxf(fw + ox, 0.f), 63.f);
                float y0f = floorf(y), x0f = floorf(x);
                float wy = y - y0f, wx = x - x0f;
                int y0 = (int)y0f, x0 = (int)x0f;
                int y1 = min(y0 + 1, 63), x1 = min(x0 + 1, 63);
                float v00 = base[(y0 * 64 + x0) * DD];
                float v01 = base[(y0 * 64 + x1) * DD];
                float v10 = base[(y1 * 64 + x0) * DD];
                float v11 = base[(y1 * 64 + x1) * DD];
                float val = (1.f - wy) * ((1.f - wx) * v00 + wx * v01)
                          +        wy  * ((1.f - wx) * v10 + wx * v11);
                sm[KV_OFF + pix * KVPIX + s * KVSTR + d] = val + oy * wk0 + ox * wk1 + bkv;
            }
        }
    }

    // ---- D) Q projection partials: col x 4-way d-split, 8 pixels ----
    {
        float acc[PIX];
        #pragma unroll
        for (int pix = 0; pix < PIX; ++pix) acc[pix] = 0.f;
        const float* wp = Wq + col;
        int d0 = dh * 64;
        for (int d = d0; d < d0 + 64; d += 4) {
            float w0 = wp[d * DD], w1 = wp[(d + 1) * DD];
            float w2 = wp[(d + 2) * DD], w3 = wp[(d + 3) * DD];
            #pragma unroll
            for (int pix = 0; pix < PIX; ++pix) {
                float4 xv = *(const float4*)&sm[HS_OFF + pix * DD + d];
                acc[pix] += xv.x * w0 + xv.y * w1 + xv.z * w2 + xv.w * w3;
            }
        }
        #pragma unroll
        for (int pix = 0; pix < PIX; ++pix)
            sm[QW_OFF + dh * 2048 + pix * DD + col] = acc[pix];
    }
    __syncthreads();
    // D-combine -> q
    {
        #pragma unroll
        for (int r = 0; r < 2; ++r) {
            int idx = t + r * 1024;
            int c2 = idx & 255;
            float q = bq[c2];
            #pragma unroll
            for (int h = 0; h < 4; ++h) q += sm[QW_OFF + h * 2048 + idx];
            sm[Q_OFF + idx] = q;
        }
    }
    __syncthreads();

    // ---- E) qw[pix][a][d] = sum_e q[pix][a*64+e] * WkT[(a*64+e)*256+d]  (scale baked) ----
    {
        int a = t >> 8, d = t & 255;
        float acc[PIX];
        #pragma unroll
        for (int pix = 0; pix < PIX; ++pix) acc[pix] = 0.f;
        const float* wp = g_WkT + a * 64 * DD + d;
        const float* qp = sm + Q_OFF + a * 64;
        #pragma unroll 4
        for (int e = 0; e < 64; e += 4) {
            float w0 = wp[e * DD], w1 = wp[(e + 1) * DD];
            float w2 = wp[(e + 2) * DD], w3 = wp[(e + 3) * DD];
            #pragma unroll
            for (int pix = 0; pix < PIX; ++pix) {
                float4 qv = *(const float4*)&qp[pix * DD + e];
                acc[pix] += qv.x * w0 + qv.y * w1 + qv.z * w2 + qv.w * w3;
            }
        }
        #pragma unroll
        for (int pix = 0; pix < PIX; ++pix)
            sm[QW_OFF + pix * 1024 + a * DD + d] = acc[pix];
    }
    __syncthreads();

    // ---- F) scores + softmax: 512 threads = 8 pix x 4 heads x 16 s ----
    if (t < 512) {
        int s = t & 15, a = (t >> 4) & 3, pix = t >> 6;
        const float* kvp = sm + KV_OFF + pix * KVPIX + s * KVSTR;
        const float* qwp = sm + QW_OFF + pix * 1024 + a * DD;
        float sc = 0.f;
        #pragma unroll 8
        for (int d = 0; d < DD; d += 4) {
            float4 kvv = *(const float4*)&kvp[d];
            float4 qw4 = *(const float4*)&qwp[d];
            sc += kvv.x * qw4.x + kvv.y * qw4.y + kvv.z * qw4.z + kvv.w * qw4.w;
        }
        float mx = sc;
        #pragma unroll
        for (int m = 8; m >= 1; m >>= 1)
            mx = fmaxf(mx, __shfl_xor_sync(0xffffffffu, mx, m, 16));
        float ex = expf(sc - mx);
        float sum = ex;
        #pragma unroll
        for (int m = 8; m >= 1; m >>= 1)
            sum += __shfl_xor_sync(0xffffffffu, sum, m, 16);
        sm[P_OFF + pix * 64 + a * 16 + s] = ex / sum;
    }
    __syncthreads();

    // ---- G) ctx[pix][a][d] = sum_s p[a,s] * kv[s,d]  (overwrites qw) ----
    {
        int pp = t >> 8, d = t & 255;
        #pragma unroll
        for (int q2 = 0; q2 < 2; ++q2) {
            int pix = pp + 4 * q2;
            const float* kvp = sm + KV_OFF + pix * KVPIX + d;
            const float* pr = sm + P_OFF + pix * 64;
            float c0 = 0.f, c1 = 0.f, c2 = 0.f, c3 = 0.f;
            #pragma unroll
            for (int s = 0; s < SS; ++s) {
                float kvv = kvp[s * KVSTR];
                c0 += pr[s] * kvv;
                c1 += pr[16 + s] * kvv;
                c2 += pr[32 + s] * kvv;
                c3 += pr[48 + s] * kvv;
            }
            float* cx = sm + QW_OFF + pix * 1024 + d;
            cx[0] = c0; cx[256] = c1; cx[512] = c2; cx[768] = c3;
        }
    }
    __syncthreads();

    // ---- H1) attn = ctx @ Wv + bv : col x 4-way d-split (partials in KV region) ----
    {
        int a = col >> 6;
        float acc[PIX];
        #pragma unroll
        for (int pix = 0; pix < PIX; ++pix) acc[pix] = 0.f;
        const float* wp = Wv + col;
        int d0 = dh * 64;
        for (int d = d0; d < d0 + 64; d += 4) {
            float w0 = wp[d * DD], w1 = wp[(d + 1) * DD];
            float w2 = wp[(d + 2) * DD], w3 = wp[(d + 3) * DD];
            #pragma unroll
            for (int pix = 0; pix < PIX; ++pix) {
                float4 cv = *(const float4*)&sm[QW_OFF + pix * 1024 + a * DD + d];
                acc[pix] += cv.x * w0 + cv.y * w1 + cv.z * w2 + cv.w * w3;
            }
        }
        #pragma unroll
        for (int pix = 0; pix < PIX; ++pix)
            sm[KV_OFF + dh * 2048 + pix * DD + col] = acc[pix];
    }
    __syncthreads();
    // H1-combine -> attn (Q buffer)
    {
        #pragma unroll
        for (int r = 0; r < 2; ++r) {
            int idx = t + r * 1024;
            int c2 = idx & 255;
            float v = bv[c2];
            #pragma unroll
            for (int h = 0; h < 4; ++h) v += sm[KV_OFF + h * 2048 + idx];
            sm[Q_OFF + idx] = v;
        }
    }
    __syncthreads();

    // ---- H2) out-proj partials: attn @ Wo ----
    {
        float acc[PIX];
        #pragma unroll
        for (int pix = 0; pix < PIX; ++pix) acc[pix] = 0.f;
        const float* wp = Wo + col;
        int d0 = dh * 64;
        for (int d = d0; d < d0 + 64; d += 4) {
            float w0 = wp[d * DD], w1 = wp[(d + 1) * DD];
            float w2 = wp[(d + 2) * DD], w3 = wp[(d + 3) * DD];
            #pragma unroll
            for (int pix = 0; pix < PIX; ++pix) {
                float4 av = *(const float4*)&sm[Q_OFF + pix * DD + d];
                acc[pix] += av.x * w0 + av.y * w1 + av.z * w2 + av.w * w3;
            }
        }
        #pragma unroll
        for (int pix = 0; pix < PIX; ++pix)
            sm[KV_OFF + dh * 2048 + pix * DD + col] = acc[pix];
    }
    __syncthreads();

    // ---- H2-combine + residual + LayerNorm1 -> x ----
    {
        int pp = t >> 8;
        float a0 = bo[col], a1 = a0;
        #pragma unroll
        for (int h = 0; h < 4; ++h) {
            a0 += sm[KV_OFF + h * 2048 + pp * DD + col];
            a1 += sm[KV_OFF + h * 2048 + (pp + 4) * DD + col];
        }
        float r0 = sm[HS_OFF + pp * DD + col] + a0;
        float r1 = sm[HS_OFF + (pp + 4) * DD + col] + a1;

        float s1a = r0, s2a = r0 * r0, s1b = r1, s2b = r1 * r1;
        #pragma unroll
        for (int m = 16; m >= 1; m >>= 1) {
            s1a += __shfl_xor_sync(0xffffffffu, s1a, m);
            s2a += __shfl_xor_sync(0xffffffffu, s2a, m);
            s1b += __shfl_xor_sync(0xffffffffu, s1b, m);
            s2b += __shfl_xor_sync(0xffffffffu, s2b, m);
        }
        int wid = t >> 5, lid = t & 31;
        if (lid == 0)
            *(float4*)&sm[RED_OFF + wid * 4] = make_float4(s1a, s2a, s1b, s2b);
        __syncthreads();
        float m1a = 0.f, m2a = 0.f, m1b = 0.f, m2b = 0.f;
        #pragma unroll
        for (int w = 0; w < 8; ++w) {
            float4 rr = *(const float4*)&sm[RED_OFF + (pp * 8 + w) * 4];
            m1a += rr.x; m2a += rr.y; m1b += rr.z; m2b += rr.w;
        }
        m1a *= (1.f / 256.f); m2a = m2a * (1.f / 256.f) - m1a * m1a;
        m1b *= (1.f / 256.f); m2b = m2b * (1.f / 256.f) - m1b * m1b;
        float g = ln1s[col], be = ln1b[col];
        sm[X_OFF + pp * DD + col] = (r0 - m1a) * rsqrtf(m2a + 1e-6f) * g + be;
        sm[X_OFF + (pp + 4) * DD + col] = (r1 - m1b) * rsqrtf(m2b + 1e-6f) * g + be;
    }
    __syncthreads();

    // ---- I) MLP1 + gelu: thread owns hidden col t, 8 pixels (kv buffer reused) ----
    {
        float acc[PIX];
        float bb = b1[t];
        #pragma unroll
        for (int pix = 0; pix < PIX; ++pix) acc[pix] = bb;
        const float* wp = W1 + t;
        for (int d = 0; d < DD; d += 4) {
            float w0 = wp[d * MLPH], w1 = wp[(d + 1) * MLPH];
            float w2 = wp[(d + 2) * MLPH], w3 = wp[(d + 3) * MLPH];
            #pragma unroll
            for (int pix = 0; pix < PIX; ++pix) {
                float4 xv = *(const float4*)&sm[X_OFF + pix * DD + d];
                acc[pix] += xv.x * w0 + xv.y * w1 + xv.z * w2 + xv.w * w3;
            }
        }
        #pragma unroll
        for (int pix = 0; pix < PIX; ++pix)
            sm[KV_OFF + pix * MLPH + t] = gelu_tanh(acc[pix]);
    }
    __syncthreads();

    // ---- J) MLP2: 4-way split over f; partials into QW buffer ----
    {
        float acc[PIX];
        #pragma unroll
        for (int pix = 0; pix < PIX; ++pix) acc[pix] = 0.f;
        const float* wp = W2 + col;
        int f0 = dh * 256;
        for (int f = f0; f < f0 + 256; f += 4) {
            float w0 = wp[f * DD], w1 = wp[(f + 1) * DD];
            float w2 = wp[(f + 2) * DD], w3 = wp[(f + 3) * DD];
            #pragma unroll
            for (int pix = 0; pix < PIX; ++pix) {
                float4 hv = *(const float4*)&sm[KV_OFF + pix * MLPH + f];
                acc[pix] += hv.x * w0 + hv.y * w1 + hv.z * w2 + hv.w * w3;
            }
        }
        #pragma unroll
        for (int pix = 0; pix < PIX; ++pix)
            sm[QW_OFF + dh * 2048 + pix * DD + col] = acc[pix];
    }
    __syncthreads();

    // ---- K) combine partials, residual, LayerNorm2, store ----
    {
        int pp = t >> 8;
        float bb = b2[col];
        float y0 = bb, y1 = bb;
        #pragma unroll
        for (int c = 0; c < 4; ++c) {
            y0 += sm[QW_OFF + c * 2048 + pp * DD + col];
            y1 += sm[QW_OFF + c * 2048 + (pp + 4) * DD + col];
        }
        float r0 = sm[X_OFF + pp * DD + col] + y0;
        float r1 = sm[X_OFF + (pp + 4) * DD + col] + y1;

        float s1a = r0, s2a = r0 * r0, s1b = r1, s2b = r1 * r1;
        #pragma unroll
        for (int m = 16; m >= 1; m >>= 1) {
            s1a += __shfl_xor_sync(0xffffffffu, s1a, m);
            s2a += __shfl_xor_sync(0xffffffffu, s2a, m);
            s1b += __shfl_xor_sync(0xffffffffu, s1b, m);
            s2b += __shfl_xor_sync(0xffffffffu, s2b, m);
        }
        int wid = t >> 5, lid = t & 31;
        __syncthreads();  // protect RED reuse
        if (lid == 0)
            *(float4*)&sm[RED_OFF + wid * 4] = make_float4(s1a, s2a, s1b, s2b);
        __syncthreads();
        float m1a = 0.f, m2a = 0.f, m1b = 0.f, m2b = 0.f;
        #pragma unroll
        for (int w = 0; w < 8; ++w) {
            float4 rr = *(const float4*)&sm[RED_OFF + (pp * 8 + w) * 4];
            m1a += rr.x; m2a += rr.y; m1b += rr.z; m2b += rr.w;
        }
        m1a *= (1.f / 256.f); m2a = m2a * (1.f / 256.f) - m1a * m1a;
        m1b *= (1.f / 256.f); m2b = m2b * (1.f / 256.f) - m1b * m1b;
        float g = ln2s[col], be = ln2b[col];
        out[((size_t)pbase + pp) * DD + col] =
            (r0 - m1a) * rsqrtf(m2a + 1e-6f) * g + be;
        out[((size_t)pbase + pp + 4) * DD + col] =
            (r1 - m1b) * rsqrtf(m2b + 1e-6f) * g + be;
    }
}

extern "C" void kernel_launch(void* const* d_in, const int* in_sizes, int n_in,
                              void* d_out, int out_size)
{
    const float* hs    = (const float*)d_in[0];
    const float* emb   = (const float*)d_in[1];
    const float* W_off = (const float*)d_in[2];
    const float* b_off = (const float*)d_in[3];
    const float* W_kvp = (const float*)d_in[4];
    const float* b_kvp = (const float*)d_in[5];
    const float* Wq = (const float*)d_in[6];  const float* bq = (const float*)d_in[7];
    const float* Wk = (const float*)d_in[8];  // bk = d_in[9] cancels in softmax
    const float* Wv = (const float*)d_in[10]; const float* bv = (const float*)d_in[11];
    const float* Wo = (const float*)d_in[12]; const float* bo = (const float*)d_in[13];
    const float* ln1s = (const float*)d_in[14]; const float* ln1b = (const float*)d_in[15];
    const float *ln2s, *ln2b, *W1, *b1, *W2, *b2;
    if (in_sizes[16] == 256) {
        ln2s = (const float*)d_in[16]; ln2b = (const float*)d_in[17];
        W1   = (const float*)d_in[18]; b1   = (const float*)d_in[19];
        W2   = (const float*)d_in[20]; b2   = (const float*)d_in[21];
    } else {
        W1   = (const float*)d_in[16]; b1   = (const float*)d_in[17];
        W2   = (const float*)d_in[18]; b2   = (const float*)d_in[19];
        ln2s = (const float*)d_in[20]; ln2b = (const float*)d_in[21];
    }
    transpose_wk<<<256, 256>>>(Wk);
    cudaFuncSetAttribute(dtb_kernel, cudaFuncAttributeMaxDynamicSharedMemorySize, SM_BYTES);
    dtb_kernel<<<8192 / PIX, NT, SM_BYTES>>>(hs, emb, W_off, b_off, W_kvp, b_kvp,
                                             Wq, bq, Wv, bv, Wo, bo,
                                             ln1s, ln1b, ln2s, ln2b, W1, b1, W2, b2,
                                             (float*)d_out);
}

// round 5
// speedup vs baseline: 3.2984x; 1.2579x over previous
#include <cuda_runtime.h>
#include <math.h>

#define DD 256
#define SS 16
#define MLPH 1024
#define PIX 8
#define NT 1024
#define KVSTR 264              // padded kv row stride (floats)
#define KVPIX (SS * KVSTR)     // 4224 floats per pixel

// dynamic smem layout (float offsets)
#define KV_OFF   0             // 33792: kv ; later H1/H2 partials[4][8][256]; I partials[2][8][1024] + h[8][1024]@+16384 ; J partials[8][8][256]
#define QW_OFF   33792         // 8192: D partials[4][8][256] -> qw[8][4][256] -> ctx[8][4][256]
#define HS_OFF   41984         // [8][256]
#define Q_OFF    44032         // [8][256] : q -> attn
#define X_OFF    46080         // [8][256]
#define OFFS_OFF 48128         // [8][32]
#define P_OFF    48384         // [8][64]
#define RED_OFF  48896         // [32][4]
#define SM_FLOATS 49024
#define SM_BYTES  (SM_FLOATS * 4)

__device__ float g_WkT[DD * DD];   // WkT[(a*64+e)*256 + d] = 0.125*Wk[d][a*64+e]

__device__ __forceinline__ float gelu_tanh(float v) {
    float c = 0.7978845608028654f * (v + 0.044715f * v * v * v);
    return 0.5f * v * (1.0f + tanhf(c));
}

__global__ void transpose_wk(const float* __restrict__ Wk) {
    int i = blockIdx.x * 256 + threadIdx.x;   // i = ae*256 + d
    int d = i & 255;
    int ae = i >> 8;
    g_WkT[i] = 0.125f * Wk[d * 256 + ae];
}

__global__ __launch_bounds__(NT, 1) void dtb_kernel(
    const float* __restrict__ hs_g, const float* __restrict__ emb_g,
    const float* __restrict__ W_off, const float* __restrict__ b_off,
    const float* __restrict__ W_kvp, const float* __restrict__ b_kvp,
    const float* __restrict__ Wq, const float* __restrict__ bq,
    const float* __restrict__ Wv, const float* __restrict__ bv,
    const float* __restrict__ Wo, const float* __restrict__ bo,
    const float* __restrict__ ln1s, const float* __restrict__ ln1b,
    const float* __restrict__ ln2s, const float* __restrict__ ln2b,
    const float* __restrict__ W1, const float* __restrict__ b1,
    const float* __restrict__ W2, const float* __restrict__ b2,
    float* __restrict__ out)
{
    extern __shared__ float sm[];
    const int t = threadIdx.x;
    const int pbase = blockIdx.x * PIX;
    const int n  = pbase >> 12;
    const int hh = (pbase >> 6) & 63;
    const int wwb = pbase & 63;

    // ---- A) load hidden state for 8 pixels ----
    {
        float2 v = *(const float2*)&hs_g[(size_t)pbase * DD + 2 * t];
        sm[HS_OFF + 2 * t] = v.x;
        sm[HS_OFF + 2 * t + 1] = v.y;
    }
    __syncthreads();

    // ---- B) offsets ----
    {
        int pix = t >> 7, o = (t >> 2) & 31, c = t & 3;
        const float* hp = sm + HS_OFF + pix * DD + c * 64;
        const float* wp = W_off + (c * 64) * 32 + o;
        float acc = 0.f;
        #pragma unroll 16
        for (int d = 0; d < 64; ++d) acc += hp[d] * wp[d * 32];
        acc += __shfl_xor_sync(0xffffffffu, acc, 1);
        acc += __shfl_xor_sync(0xffffffffu, acc, 2);
        if (c == 0) {
            float z = acc + b_off[o];
            sm[OFFS_OFF + pix * 32 + o] = 60.0f / (1.0f + expf(-z)) - 30.0f;
        }
    }
    __syncthreads();

    // ---- C) bilinear gather + offset embedding -> kv ----
    {
        int pp = t >> 8, d = t & 255;
        float wk0 = W_kvp[d], wk1 = W_kvp[DD + d], bkv = b_kvp[d];
        const float* base = emb_g + (size_t)n * 64 * 64 * DD + d;
        float fh = (float)hh;
        #pragma unroll
        for (int q2 = 0; q2 < 2; ++q2) {
            int pix = pp + 4 * q2;
            float fw = (float)(wwb + pix);
            #pragma unroll 4
            for (int s = 0; s < SS; ++s) {
                float oy = sm[OFFS_OFF + pix * 32 + 2 * s];
                float ox = sm[OFFS_OFF + pix * 32 + 2 * s + 1];
                float y = fminf(fmaxf(fh + oy, 0.f), 63.f);
                float x = fminf(fmaxf(fw + ox, 0.f), 63.f);
                float y0f = floorf(y), x0f = floorf(x);
                float wy = y - y0f, wx = x - x0f;
                int y0 = (int)y0f, x0 = (int)x0f;
                int y1 = min(y0 + 1, 63), x1 = min(x0 + 1, 63);
                float v00 = base[(y0 * 64 + x0) * DD];
                float v01 = base[(y0 * 64 + x1) * DD];
                float v10 = base[(y1 * 64 + x0) * DD];
                float v11 = base[(y1 * 64 + x1) * DD];
                float val = (1.f - wy) * ((1.f - wx) * v00 + wx * v01)
                          +        wy  * ((1.f - wx) * v10 + wx * v11);
                sm[KV_OFF + pix * KVPIX + s * KVSTR + d] = val + oy * wk0 + ox * wk1 + bkv;
            }
        }
    }

    // ---- D) Q projection: 2 cols x 4 pix x 4-way d-split ----
    {
        int dh = t >> 8, rem = t & 255, ph = rem >> 7, cg = rem & 127;
        int c0 = 2 * cg, pixb = ph * 4;
        float acc[4][2];
        #pragma unroll
        for (int i = 0; i < 4; ++i) { acc[i][0] = 0.f; acc[i][1] = 0.f; }
        const float* wp = Wq + c0;
        int d0 = dh * 64;
        for (int d = d0; d < d0 + 64; d += 4) {
            float2 w0 = *(const float2*)&wp[d * DD];
            float2 w1 = *(const float2*)&wp[(d + 1) * DD];
            float2 w2 = *(const float2*)&wp[(d + 2) * DD];
            float2 w3 = *(const float2*)&wp[(d + 3) * DD];
            #pragma unroll
            for (int i = 0; i < 4; ++i) {
                float4 xv = *(const float4*)&sm[HS_OFF + (pixb + i) * DD + d];
                acc[i][0] += xv.x * w0.x + xv.y * w1.x + xv.z * w2.x + xv.w * w3.x;
                acc[i][1] += xv.x * w0.y + xv.y * w1.y + xv.z * w2.y + xv.w * w3.y;
            }
        }
        #pragma unroll
        for (int i = 0; i < 4; ++i)
            *(float2*)&sm[QW_OFF + dh * 2048 + (pixb + i) * 256 + c0] =
                make_float2(acc[i][0], acc[i][1]);
    }
    __syncthreads();
    // D-combine -> q (+bq)
    {
        int fi = 2 * t, c0 = fi & 255;
        float2 v = *(const float2*)&bq[c0];
        #pragma unroll
        for (int h = 0; h < 4; ++h) {
            float2 p2 = *(const float2*)&sm[QW_OFF + h * 2048 + fi];
            v.x += p2.x; v.y += p2.y;
        }
        *(float2*)&sm[Q_OFF + fi] = v;
    }
    __syncthreads();

    // ---- E) qw[pix][a][d] = sum_e q[pix][a*64+e]*WkT[ae][d] : 2 d-cols x 4 pix ----
    {
        int a = t >> 8, rem = t & 255, ph = rem >> 7, cg = rem & 127;
        int c0 = 2 * cg, pixb = ph * 4;
        float acc[4][2];
        #pragma unroll
        for (int i = 0; i < 4; ++i) { acc[i][0] = 0.f; acc[i][1] = 0.f; }
        const float* wp = g_WkT + a * 64 * DD + c0;
        const float* qp = sm + Q_OFF + a * 64;
        #pragma unroll 4
        for (int e = 0; e < 64; e += 4) {
            float2 w0 = *(const float2*)&wp[e * DD];
            float2 w1 = *(const float2*)&wp[(e + 1) * DD];
            float2 w2 = *(const float2*)&wp[(e + 2) * DD];
            float2 w3 = *(const float2*)&wp[(e + 3) * DD];
            #pragma unroll
            for (int i = 0; i < 4; ++i) {
                float4 qv = *(const float4*)&qp[(pixb + i) * DD + e];
                acc[i][0] += qv.x * w0.x + qv.y * w1.x + qv.z * w2.x + qv.w * w3.x;
                acc[i][1] += qv.x * w0.y + qv.y * w1.y + qv.z * w2.y + qv.w * w3.y;
            }
        }
        #pragma unroll
        for (int i = 0; i < 4; ++i)
            *(float2*)&sm[QW_OFF + (pixb + i) * 1024 + a * 256 + c0] =
                make_float2(acc[i][0], acc[i][1]);
    }
    __syncthreads();

    // ---- F) scores + softmax: 512 threads = 8 pix x 4 heads x 16 s ----
    if (t < 512) {
        int s = t & 15, a = (t >> 4) & 3, pix = t >> 6;
        const float* kvp = sm + KV_OFF + pix * KVPIX + s * KVSTR;
        const float* qwp = sm + QW_OFF + pix * 1024 + a * DD;
        float sc = 0.f;
        #pragma unroll 8
        for (int d = 0; d < DD; d += 4) {
            float4 kvv = *(const float4*)&kvp[d];
            float4 qw4 = *(const float4*)&qwp[d];
            sc += kvv.x * qw4.x + kvv.y * qw4.y + kvv.z * qw4.z + kvv.w * qw4.w;
        }
        float mx = sc;
        #pragma unroll
        for (int m = 8; m >= 1; m >>= 1)
            mx = fmaxf(mx, __shfl_xor_sync(0xffffffffu, mx, m, 16));
        float ex = expf(sc - mx);
        float sum = ex;
        #pragma unroll
        for (int m = 8; m >= 1; m >>= 1)
            sum += __shfl_xor_sync(0xffffffffu, sum, m, 16);
        sm[P_OFF + pix * 64 + a * 16 + s] = ex / sum;
    }
    __syncthreads();

    // ---- G) ctx[pix][a][d] = sum_s p[a,s]*kv[s,d] : 1 pix x 2 d-cols, kv cached ----
    {
        int pix = t >> 7, cg = t & 127, c0 = 2 * cg;
        const float* kvp = sm + KV_OFF + pix * KVPIX + c0;
        const float* pr = sm + P_OFF + pix * 64;
        float2 kvv[SS];
        #pragma unroll
        for (int s = 0; s < SS; ++s) kvv[s] = *(const float2*)&kvp[s * KVSTR];
        #pragma unroll
        for (int a = 0; a < 4; ++a) {
            float cx = 0.f, cy = 0.f;
            #pragma unroll
            for (int s = 0; s < SS; ++s) {
                float p = pr[a * 16 + s];
                cx += p * kvv[s].x;
                cy += p * kvv[s].y;
            }
            *(float2*)&sm[QW_OFF + pix * 1024 + a * 256 + c0] = make_float2(cx, cy);
        }
    }
    __syncthreads();

    // ---- H1) attn = ctx @ Wv : 2 cols x 4 pix x 4-way d-split (partials -> KV) ----
    {
        int dh = t >> 8, rem = t & 255, ph = rem >> 7, cg = rem & 127;
        int c0 = 2 * cg, pixb = ph * 4, a = c0 >> 6;
        float acc[4][2];
        #pragma unroll
        for (int i = 0; i < 4; ++i) { acc[i][0] = 0.f; acc[i][1] = 0.f; }
        const float* wp = Wv + c0;
        int d0 = dh * 64;
        for (int d = d0; d < d0 + 64; d += 4) {
            float2 w0 = *(const float2*)&wp[d * DD];
            float2 w1 = *(const float2*)&wp[(d + 1) * DD];
            float2 w2 = *(const float2*)&wp[(d + 2) * DD];
            float2 w3 = *(const float2*)&wp[(d + 3) * DD];
            #pragma unroll
            for (int i = 0; i < 4; ++i) {
                float4 cv = *(const float4*)&sm[QW_OFF + (pixb + i) * 1024 + a * 256 + d];
                acc[i][0] += cv.x * w0.x + cv.y * w1.x + cv.z * w2.x + cv.w * w3.x;
                acc[i][1] += cv.x * w0.y + cv.y * w1.y + cv.z * w2.y + cv.w * w3.y;
            }
        }
        #pragma unroll
        for (int i = 0; i < 4; ++i)
            *(float2*)&sm[KV_OFF + dh * 2048 + (pixb + i) * 256 + c0] =
                make_float2(acc[i][0], acc[i][1]);
    }
    __syncthreads();
    // H1-combine -> attn (+bv) into Q buffer
    {
        int fi = 2 * t, c0 = fi & 255;
        float2 v = *(const float2*)&bv[c0];
        #pragma unroll
        for (int h = 0; h < 4; ++h) {
            float2 p2 = *(const float2*)&sm[KV_OFF + h * 2048 + fi];
            v.x += p2.x; v.y += p2.y;
        }
        *(float2*)&sm[Q_OFF + fi] = v;
    }
    __syncthreads();

    // ---- H2) out-proj: attn @ Wo : 2 cols x 4 pix x 4-way d-split ----
    {
        int dh = t >> 8, rem = t & 255, ph = rem >> 7, cg = rem & 127;
        int c0 = 2 * cg, pixb = ph * 4;
        float acc[4][2];
        #pragma unroll
        for (int i = 0; i < 4; ++i) { acc[i][0] = 0.f; acc[i][1] = 0.f; }
        const float* wp = Wo + c0;
        int d0 = dh * 64;
        for (int d = d0; d < d0 + 64; d += 4) {
            float2 w0 = *(const float2*)&wp[d * DD];
            float2 w1 = *(const float2*)&wp[(d + 1) * DD];
            float2 w2 = *(const float2*)&wp[(d + 2) * DD];
            float2 w3 = *(const float2*)&wp[(d + 3) * DD];
            #pragma unroll
            for (int i = 0; i < 4; ++i) {
                float4 av = *(const float4*)&sm[Q_OFF + (pixb + i) * 256 + d];
                acc[i][0] += av.x * w0.x + av.y * w1.x + av.z * w2.x + av.w * w3.x;
                acc[i][1] += av.x * w0.y + av.y * w1.y + av.z * w2.y + av.w * w3.y;
            }
        }
        #pragma unroll
        for (int i = 0; i < 4; ++i)
            *(float2*)&sm[KV_OFF + dh * 2048 + (pixb + i) * 256 + c0] =
                make_float2(acc[i][0], acc[i][1]);
    }
    __syncthreads();

    // ---- H2-combine + residual + LayerNorm1 -> x ----
    {
        int pp = t >> 8, col = t & 255;
        float a0 = bo[col], a1 = a0;
        #pragma unroll
        for (int h = 0; h < 4; ++h) {
            a0 += sm[KV_OFF + h * 2048 + pp * DD + col];
            a1 += sm[KV_OFF + h * 2048 + (pp + 4) * DD + col];
        }
        float r0 = sm[HS_OFF + pp * DD + col] + a0;
        float r1 = sm[HS_OFF + (pp + 4) * DD + col] + a1;

        float s1a = r0, s2a = r0 * r0, s1b = r1, s2b = r1 * r1;
        #pragma unroll
        for (int m = 16; m >= 1; m >>= 1) {
            s1a += __shfl_xor_sync(0xffffffffu, s1a, m);
            s2a += __shfl_xor_sync(0xffffffffu, s2a, m);
            s1b += __shfl_xor_sync(0xffffffffu, s1b, m);
            s2b += __shfl_xor_sync(0xffffffffu, s2b, m);
        }
        int wid = t >> 5, lid = t & 31;
        if (lid == 0)
            *(float4*)&sm[RED_OFF + wid * 4] = make_float4(s1a, s2a, s1b, s2b);
        __syncthreads();
        float m1a = 0.f, m2a = 0.f, m1b = 0.f, m2b = 0.f;
        #pragma unroll
        for (int w = 0; w < 8; ++w) {
            float4 rr = *(const float4*)&sm[RED_OFF + (pp * 8 + w) * 4];
            m1a += rr.x; m2a += rr.y; m1b += rr.z; m2b += rr.w;
        }
        m1a *= (1.f / 256.f); m2a = m2a * (1.f / 256.f) - m1a * m1a;
        m1b *= (1.f / 256.f); m2b = m2b * (1.f / 256.f) - m1b * m1b;
        float g = ln1s[col], be = ln1b[col];
        sm[X_OFF + pp * DD + col] = (r0 - m1a) * rsqrtf(m2a + 1e-6f) * g + be;
        sm[X_OFF + (pp + 4) * DD + col] = (r1 - m1b) * rsqrtf(m2b + 1e-6f) * g + be;
    }
    __syncthreads();

    // ---- I) MLP1: 2 cols x 8 pix x 2-way d-split (partials -> KV) ----
    {
        int dh = t >> 9, rem = t & 511, c0 = 2 * rem;
        float acc[PIX][2];
        #pragma unroll
        for (int pix = 0; pix < PIX; ++pix) { acc[pix][0] = 0.f; acc[pix][1] = 0.f; }
        const float* wp = W1 + c0;
        int d0 = dh * 128;
        for (int d = d0; d < d0 + 128; d += 4) {
            float2 w0 = *(const float2*)&wp[d * MLPH];
            float2 w1 = *(const float2*)&wp[(d + 1) * MLPH];
            float2 w2 = *(const float2*)&wp[(d + 2) * MLPH];
            float2 w3 = *(const float2*)&wp[(d + 3) * MLPH];
            #pragma unroll
            for (int pix = 0; pix < PIX; ++pix) {
                float4 xv = *(const float4*)&sm[X_OFF + pix * DD + d];
                acc[pix][0] += xv.x * w0.x + xv.y * w1.x + xv.z * w2.x + xv.w * w3.x;
                acc[pix][1] += xv.x * w0.y + xv.y * w1.y + xv.z * w2.y + xv.w * w3.y;
            }
        }
        #pragma unroll
        for (int pix = 0; pix < PIX; ++pix)
            *(float2*)&sm[KV_OFF + dh * 8192 + pix * 1024 + c0] =
                make_float2(acc[pix][0], acc[pix][1]);
    }
    __syncthreads();
    // I-combine + gelu -> h at KV_OFF+16384
    {
        #pragma unroll
        for (int r = 0; r < 4; ++r) {
            int fi = 2 * (t + r * 1024);
            int col = fi & 1023;
            float2 p0 = *(const float2*)&sm[KV_OFF + fi];
            float2 p1 = *(const float2*)&sm[KV_OFF + 8192 + fi];
            float2 bb = *(const float2*)&b1[col];
            float h0 = gelu_tanh(p0.x + p1.x + bb.x);
            float h1 = gelu_tanh(p0.y + p1.y + bb.y);
            *(float2*)&sm[KV_OFF + 16384 + fi] = make_float2(h0, h1);
        }
    }
    __syncthreads();

    // ---- J) MLP2: 2 cols x 8 pix x 8-way f-split (partials -> KV[0..16383]) ----
    {
        int dh = t >> 7, cg = t & 127, c0 = 2 * cg;
        float acc[PIX][2];
        #pragma unroll
        for (int pix = 0; pix < PIX; ++pix) { acc[pix][0] = 0.f; acc[pix][1] = 0.f; }
        const float* wp = W2 + c0;
        int f0 = dh * 128;
        for (int f = f0; f < f0 + 128; f += 4) {
            float2 w0 = *(const float2*)&wp[f * DD];
            float2 w1 = *(const float2*)&wp[(f + 1) * DD];
            float2 w2 = *(const float2*)&wp[(f + 2) * DD];
            float2 w3 = *(const float2*)&wp[(f + 3) * DD];
            #pragma unroll
            for (int pix = 0; pix < PIX; ++pix) {
                float4 hv = *(const float4*)&sm[KV_OFF + 16384 + pix * 1024 + f];
                acc[pix][0] += hv.x * w0.x + hv.y * w1.x + hv.z * w2.x + hv.w * w3.x;
                acc[pix][1] += hv.x * w0.y + hv.y * w1.y + hv.z * w2.y + hv.w * w3.y;
            }
        }
        #pragma unroll
        for (int pix = 0; pix < PIX; ++pix)
            *(float2*)&sm[KV_OFF + dh * 2048 + pix * 256 + c0] =
                make_float2(acc[pix][0], acc[pix][1]);
    }
    __syncthreads();

    // ---- K) combine 8 partials, residual, LayerNorm2, store ----
    {
        int pp = t >> 8, col = t & 255;
        float bb = b2[col];
        float y0 = bb, y1 = bb;
        #pragma unroll
        for (int c = 0; c < 8; ++c) {
            y0 += sm[KV_OFF + c * 2048 + pp * DD + col];
            y1 += sm[KV_OFF + c * 2048 + (pp + 4) * DD + col];
        }
        float r0 = sm[X_OFF + pp * DD + col] + y0;
        float r1 = sm[X_OFF + (pp + 4) * DD + col] + y1;

        float s1a = r0, s2a = r0 * r0, s1b = r1, s2b = r1 * r1;
        #pragma unroll
        for (int m = 16; m >= 1; m >>= 1) {
            s1a += __shfl_xor_sync(0xffffffffu, s1a, m);
            s2a += __shfl_xor_sync(0xffffffffu, s2a, m);
            s1b += __shfl_xor_sync(0xffffffffu, s1b, m);
            s2b += __shfl_xor_sync(0xffffffffu, s2b, m);
        }
        int wid = t >> 5, lid = t & 31;
        __syncthreads();  // protect RED reuse
        if (lid == 0)
            *(float4*)&sm[RED_OFF + wid * 4] = make_float4(s1a, s2a, s1b, s2b);
        __syncthreads();
        float m1a = 0.f, m2a = 0.f, m1b = 0.f, m2b = 0.f;
        #pragma unroll
        for (int w = 0; w < 8; ++w) {
            float4 rr = *(const float4*)&sm[RED_OFF + (pp * 8 + w) * 4];
            m1a += rr.x; m2a += rr.y; m1b += rr.z; m2b += rr.w;
        }
        m1a *= (1.f / 256.f); m2a = m2a * (1.f / 256.f) - m1a * m1a;
        m1b *= (1.f / 256.f); m2b = m2b * (1.f / 256.f) - m1b * m1b;
        float g = ln2s[col], be = ln2b[col];
        out[((size_t)pbase + pp) * DD + col] =
            (r0 - m1a) * rsqrtf(m2a + 1e-6f) * g + be;
        out[((size_t)pbase + pp + 4) * DD + col] =
            (r1 - m1b) * rsqrtf(m2b + 1e-6f) * g + be;
    }
}

extern "C" void kernel_launch(void* const* d_in, const int* in_sizes, int n_in,
                              void* d_out, int out_size)
{
    const float* hs    = (const float*)d_in[0];
    const float* emb   = (const float*)d_in[1];
    const float* W_off = (const float*)d_in[2];
    const float* b_off = (const float*)d_in[3];
    const float* W_kvp = (const float*)d_in[4];
    const float* b_kvp = (const float*)d_in[5];
    const float* Wq = (const float*)d_in[6];  const float* bq = (const float*)d_in[7];
    const float* Wk = (const float*)d_in[8];  // bk cancels in softmax
    const float* Wv = (const float*)d_in[10]; const float* bv = (const float*)d_in[11];
    const float* Wo = (const float*)d_in[12]; const float* bo = (const float*)d_in[13];
    const float* ln1s = (const float*)d_in[14]; const float* ln1b = (const float*)d_in[15];
    const float *ln2s, *ln2b, *W1, *b1, *W2, *b2;
    if (in_sizes[16] == 256) {
        ln2s = (const float*)d_in[16]; ln2b = (const float*)d_in[17];
        W1   = (const float*)d_in[18]; b1   = (const float*)d_in[19];
        W2   = (const float*)d_in[20]; b2   = (const float*)d_in[21];
    } else {
        W1   = (const float*)d_in[16]; b1   = (const float*)d_in[17];
        W2   = (const float*)d_in[18]; b2   = (const float*)d_in[19];
        ln2s = (const float*)d_in[20]; ln2b = (const float*)d_in[21];
    }
    transpose_wk<<<256, 256>>>(Wk);
    cudaFuncSetAttribute(dtb_kernel, cudaFuncAttributeMaxDynamicSharedMemorySize, SM_BYTES);
    dtb_kernel<<<8192 / PIX, NT, SM_BYTES>>>(hs, emb, W_off, b_off, W_kvp, b_kvp,
                                             Wq, bq, Wv, bv, Wo, bo,
                                             ln1s, ln1b, ln2s, ln2b, W1, b1, W2, b2,
                                             (float*)d_out);
}